// round 4
// baseline (speedup 1.0000x reference)
#include <cuda_runtime.h>
#include <cuda_bf16.h>

// Problem shape (fixed by the dataset): [B=32, C=1, H=1024, W=1024] fp32.
#define B_DIM 32
#define HW (1024 * 1024)
#define HW4 (HW / 4)
#define GRID (HW4 / 256)
#define LAMBDA 0.1

// Global accumulators: [0]=diff2, [1]=G2, [2]=H2. Zero at module load;
// the last block of each launch resets them for the next graph replay.
__device__ double g_acc[3];
__device__ unsigned int g_count;

__device__ __forceinline__ float4 ldcs4(const float4* p) {
    return __ldcs(p);
}

__global__ __launch_bounds__(256, 6) void praloss_fused_kernel(
    const float4* __restrict__ est, const float4* __restrict__ gt,
    float* __restrict__ out)
{
    const int pix4 = blockIdx.x * blockDim.x + threadIdx.x;  // 0 .. HW4-1

    // Per-pixel accumulators: sum of (e-g), sum e^2, sum (e-g)^2.
    float4 s_d = make_float4(0.f, 0.f, 0.f, 0.f);
    float4 q_e = make_float4(0.f, 0.f, 0.f, 0.f);
    float4 q_d = make_float4(0.f, 0.f, 0.f, 0.f);

    const float4* pe = est + pix4;
    const float4* pg = gt  + pix4;

    // 2-deep load-ahead pipeline over the batch dim, unrolled by 2.
    float4 e0 = ldcs4(pe);            float4 g0 = ldcs4(pg);
    float4 e1 = ldcs4(pe + HW4);      float4 g1 = ldcs4(pg + HW4);

    #pragma unroll
    for (int b = 0; b < B_DIM; b += 2) {
        float4 e2, g2, e3, g3;
        if (b + 2 < B_DIM) {
            e2 = ldcs4(pe + (long)(b + 2) * HW4);
            g2 = ldcs4(pg + (long)(b + 2) * HW4);
            e3 = ldcs4(pe + (long)(b + 3) * HW4);
            g3 = ldcs4(pg + (long)(b + 3) * HW4);
        }
        // accumulate e0/g0
        {
            float dx = e0.x - g0.x, dy = e0.y - g0.y, dz = e0.z - g0.z, dw = e0.w - g0.w;
            s_d.x += dx; s_d.y += dy; s_d.z += dz; s_d.w += dw;
            q_d.x = fmaf(dx, dx, q_d.x); q_d.y = fmaf(dy, dy, q_d.y);
            q_d.z = fmaf(dz, dz, q_d.z); q_d.w = fmaf(dw, dw, q_d.w);
            q_e.x = fmaf(e0.x, e0.x, q_e.x); q_e.y = fmaf(e0.y, e0.y, q_e.y);
            q_e.z = fmaf(e0.z, e0.z, q_e.z); q_e.w = fmaf(e0.w, e0.w, q_e.w);
        }
        // accumulate e1/g1
        {
            float dx = e1.x - g1.x, dy = e1.y - g1.y, dz = e1.z - g1.z, dw = e1.w - g1.w;
            s_d.x += dx; s_d.y += dy; s_d.z += dz; s_d.w += dw;
            q_d.x = fmaf(dx, dx, q_d.x); q_d.y = fmaf(dy, dy, q_d.y);
            q_d.z = fmaf(dz, dz, q_d.z); q_d.w = fmaf(dw, dw, q_d.w);
            q_e.x = fmaf(e1.x, e1.x, q_e.x); q_e.y = fmaf(e1.y, e1.y, q_e.y);
            q_e.z = fmaf(e1.z, e1.z, q_e.z); q_e.w = fmaf(e1.w, e1.w, q_e.w);
        }
        e0 = e2; g0 = g2; e1 = e3; g1 = g3;
    }

    float diff2 = q_d.x + q_d.y + q_d.z + q_d.w;
    float G2    = q_e.x + q_e.y + q_e.z + q_e.w;
    // mask: sum(est) > sum(gt)  <=>  sum(est - gt) > 0 (up to fp rounding)
    float H2    = (s_d.x > 0.f ? q_e.x : 0.f)
                + (s_d.y > 0.f ? q_e.y : 0.f)
                + (s_d.z > 0.f ? q_e.z : 0.f)
                + (s_d.w > 0.f ? q_e.w : 0.f);

    // Warp reduce (3 scalars)
    #pragma unroll
    for (int off = 16; off > 0; off >>= 1) {
        diff2 += __shfl_down_sync(0xFFFFFFFFu, diff2, off);
        G2    += __shfl_down_sync(0xFFFFFFFFu, G2,    off);
        H2    += __shfl_down_sync(0xFFFFFFFFu, H2,    off);
    }

    // Block reduce via shared memory (8 warps)
    __shared__ float sm[3][8];
    const int lane = threadIdx.x & 31;
    const int wid  = threadIdx.x >> 5;
    if (lane == 0) {
        sm[0][wid] = diff2; sm[1][wid] = G2; sm[2][wid] = H2;
    }
    __syncthreads();

    if (threadIdx.x == 0) {
        float v0 = 0.f, v1 = 0.f, v2 = 0.f;
        #pragma unroll
        for (int w = 0; w < 8; w++) {
            v0 += sm[0][w]; v1 += sm[1][w]; v2 += sm[2][w];
        }
        atomicAdd(&g_acc[0], (double)v0);
        atomicAdd(&g_acc[1], (double)v1);
        atomicAdd(&g_acc[2], (double)v2);

        __threadfence();
        unsigned int old = atomicAdd(&g_count, 1u);
        if (old == (unsigned int)(GRID - 1)) {
            double diff2d = atomicAdd(&g_acc[0], 0.0);
            double G2d    = atomicAdd(&g_acc[1], 0.0);
            double H2d    = atomicAdd(&g_acc[2], 0.0);
            out[0] = (float)(diff2d / G2d + LAMBDA * (diff2d / H2d));
            // Reset for next replay (only this block is still running).
            atomicExch((unsigned long long*)&g_acc[0], 0ull);
            atomicExch((unsigned long long*)&g_acc[1], 0ull);
            atomicExch((unsigned long long*)&g_acc[2], 0ull);
            __threadfence();
            atomicExch(&g_count, 0u);
        }
    }
}

extern "C" void kernel_launch(void* const* d_in, const int* in_sizes, int n_in,
                              void* d_out, int out_size) {
    const float4* est = (const float4*)d_in[0];
    const float4* gt  = (const float4*)d_in[1];
    float* out = (float*)d_out;

    praloss_fused_kernel<<<GRID, 256>>>(est, gt, out);
}

// round 6
// speedup vs baseline: 1.2706x; 1.2706x over previous
#include <cuda_runtime.h>
#include <cuda_bf16.h>

// Problem shape (fixed by the dataset): [B=32, C=1, H=1024, W=1024] fp32.
#define B_DIM 32
#define HW (1024 * 1024)
#define HW4 (HW / 4)          // 262144 float4 pixels
#define HALF (HW4 / 2)        // 131072: each thread handles pix4 and pix4+HALF
#define GRID (HALF / 256)     // 512 blocks -> single wave at >=4 blocks/SM
#define LAMBDA 0.1

// Global accumulators: [0]=diff2, [1]=G2, [2]=H2
__device__ double g_acc[3];

__global__ void init_kernel() {
    if (threadIdx.x < 3) g_acc[threadIdx.x] = 0.0;
}

__global__ __launch_bounds__(256, 4) void praloss_main_kernel(
    const float4* __restrict__ est, const float4* __restrict__ gt)
{
    const int pix4 = blockIdx.x * blockDim.x + threadIdx.x;  // 0 .. HALF-1

    // Per-pixel accumulators for two pixels: sum(e-g), sum e^2, sum (e-g)^2.
    float4 sd0 = make_float4(0.f, 0.f, 0.f, 0.f);
    float4 qe0 = make_float4(0.f, 0.f, 0.f, 0.f);
    float4 qd0 = make_float4(0.f, 0.f, 0.f, 0.f);
    float4 sd1 = make_float4(0.f, 0.f, 0.f, 0.f);
    float4 qe1 = make_float4(0.f, 0.f, 0.f, 0.f);
    float4 qd1 = make_float4(0.f, 0.f, 0.f, 0.f);

    const float4* pe = est + pix4;
    const float4* pg = gt  + pix4;

    #pragma unroll 4
    for (int b = 0; b < B_DIM; b++) {
        const long off = (long)b * HW4;
        const float4 e0 = pe[off];
        const float4 g0 = pg[off];
        const float4 e1 = pe[off + HALF];
        const float4 g1 = pg[off + HALF];

        float dx, dy, dz, dw;
        dx = e0.x - g0.x; dy = e0.y - g0.y; dz = e0.z - g0.z; dw = e0.w - g0.w;
        sd0.x += dx; sd0.y += dy; sd0.z += dz; sd0.w += dw;
        qd0.x = fmaf(dx, dx, qd0.x); qd0.y = fmaf(dy, dy, qd0.y);
        qd0.z = fmaf(dz, dz, qd0.z); qd0.w = fmaf(dw, dw, qd0.w);
        qe0.x = fmaf(e0.x, e0.x, qe0.x); qe0.y = fmaf(e0.y, e0.y, qe0.y);
        qe0.z = fmaf(e0.z, e0.z, qe0.z); qe0.w = fmaf(e0.w, e0.w, qe0.w);

        dx = e1.x - g1.x; dy = e1.y - g1.y; dz = e1.z - g1.z; dw = e1.w - g1.w;
        sd1.x += dx; sd1.y += dy; sd1.z += dz; sd1.w += dw;
        qd1.x = fmaf(dx, dx, qd1.x); qd1.y = fmaf(dy, dy, qd1.y);
        qd1.z = fmaf(dz, dz, qd1.z); qd1.w = fmaf(dw, dw, qd1.w);
        qe1.x = fmaf(e1.x, e1.x, qe1.x); qe1.y = fmaf(e1.y, e1.y, qe1.y);
        qe1.z = fmaf(e1.z, e1.z, qe1.z); qe1.w = fmaf(e1.w, e1.w, qe1.w);
    }

    float diff2 = (qd0.x + qd0.y) + (qd0.z + qd0.w)
                + (qd1.x + qd1.y) + (qd1.z + qd1.w);
    float G2    = (qe0.x + qe0.y) + (qe0.z + qe0.w)
                + (qe1.x + qe1.y) + (qe1.z + qe1.w);
    // mask: sum(est) > sum(gt) <=> sum(est-gt) > 0 (up to fp rounding)
    float H2    = (sd0.x > 0.f ? qe0.x : 0.f)
                + (sd0.y > 0.f ? qe0.y : 0.f)
                + (sd0.z > 0.f ? qe0.z : 0.f)
                + (sd0.w > 0.f ? qe0.w : 0.f)
                + (sd1.x > 0.f ? qe1.x : 0.f)
                + (sd1.y > 0.f ? qe1.y : 0.f)
                + (sd1.z > 0.f ? qe1.z : 0.f)
                + (sd1.w > 0.f ? qe1.w : 0.f);

    // Warp reduce (3 scalars)
    #pragma unroll
    for (int off = 16; off > 0; off >>= 1) {
        diff2 += __shfl_down_sync(0xFFFFFFFFu, diff2, off);
        G2    += __shfl_down_sync(0xFFFFFFFFu, G2,    off);
        H2    += __shfl_down_sync(0xFFFFFFFFu, H2,    off);
    }

    // Block reduce via shared memory (8 warps)
    __shared__ float sm[3][8];
    const int lane = threadIdx.x & 31;
    const int wid  = threadIdx.x >> 5;
    if (lane == 0) {
        sm[0][wid] = diff2; sm[1][wid] = G2; sm[2][wid] = H2;
    }
    __syncthreads();

    if (threadIdx.x == 0) {
        float v0 = 0.f, v1 = 0.f, v2 = 0.f;
        #pragma unroll
        for (int w = 0; w < 8; w++) {
            v0 += sm[0][w]; v1 += sm[1][w]; v2 += sm[2][w];
        }
        atomicAdd(&g_acc[0], (double)v0);
        atomicAdd(&g_acc[1], (double)v1);
        atomicAdd(&g_acc[2], (double)v2);
    }
}

__global__ void final_kernel(float* __restrict__ out) {
    if (threadIdx.x == 0) {
        double diff2 = g_acc[0];
        double G2    = g_acc[1];
        double H2    = g_acc[2];
        out[0] = (float)(diff2 / G2 + LAMBDA * (diff2 / H2));
    }
}

extern "C" void kernel_launch(void* const* d_in, const int* in_sizes, int n_in,
                              void* d_out, int out_size) {
    const float4* est = (const float4*)d_in[0];
    const float4* gt  = (const float4*)d_in[1];
    float* out = (float*)d_out;

    init_kernel<<<1, 32>>>();
    praloss_main_kernel<<<GRID, 256>>>(est, gt);
    final_kernel<<<1, 32>>>(out);
}